// round 1
// baseline (speedup 1.0000x reference)
#include <cuda_runtime.h>

#define NN 50000
#define NE 600000
#define HID 128
#define NT 256

// ---------------- scratch (device globals; no allocation) ----------------
__device__ float g_h[NN * HID];
__device__ float g_agg[NN * HID];
__device__ float g_sumexp[NN];
__device__ float g_scores[NE];
__device__ float g_es[NE];
__device__ int   g_src[NE];
__device__ int   g_dst[NE];
__device__ unsigned g_maxenc;
__device__ int   g_is64;

__device__ __forceinline__ unsigned fenc(float f) {
    unsigned u = __float_as_uint(f);
    return (u & 0x80000000u) ? ~u : (u | 0x80000000u);
}
__device__ __forceinline__ float fdec(unsigned u) {
    return (u & 0x80000000u) ? __uint_as_float(u & 0x7fffffffu)
                             : __uint_as_float(~u);
}

// ---------------- dtype detection + index conversion ----------------
__global__ void k_detect(const unsigned* __restrict__ raw) {
    __shared__ int nz;
    if (threadIdx.x == 0) nz = 0;
    __syncthreads();
    // If int64 (little-endian), high words of first 2048 values are all 0
    // (values < 50000). If int32, these words are random src ids (~never all 0).
    for (int i = threadIdx.x; i < 2048; i += NT)
        if (raw[2 * i + 1] != 0u) atomicOr(&nz, 1);
    __syncthreads();
    if (threadIdx.x == 0) g_is64 = (nz == 0) ? 1 : 0;
}

__global__ void k_convert(const void* __restrict__ eidx) {
    int i = blockIdx.x * blockDim.x + threadIdx.x;
    if (i >= NE) return;
    if (g_is64) {
        const long long* p = (const long long*)eidx;
        g_src[i] = (int)p[i];
        g_dst[i] = (int)p[NE + i];
    } else {
        const int* p = (const int*)eidx;
        g_src[i] = p[i];
        g_dst[i] = p[NE + i];
    }
}

// ---------------- per-layer reset ----------------
__global__ void k_reset() {
    long long tot = (long long)NN * HID;
    long long stride = (long long)gridDim.x * blockDim.x;
    long long i0 = (long long)blockIdx.x * blockDim.x + threadIdx.x;
    for (long long i = i0; i < tot; i += stride) {
        g_agg[i] = 0.f;
        if (i < NN) g_sumexp[i] = 0.f;
    }
    if (i0 == 0) g_maxenc = 0x007FFFFFu;  // fenc(-inf)
}

// ---------------- node projection: h = relu(x @ W^T + b) ----------------
// block = 256 thr, 32 nodes, K=32, OUT=128
__global__ void k_nodeproj(const float* __restrict__ x,
                           const float* __restrict__ W,
                           const float* __restrict__ b) {
    __shared__ float sA[32 * 33];
    __shared__ float sW[128 * 33];
    int tid = threadIdx.x;
    int n0 = blockIdx.x * 32;
    for (int idx = tid; idx < 32 * 32; idx += NT) {
        int r = idx >> 5, k = idx & 31;
        int n = n0 + r;
        sA[r * 33 + k] = (n < NN) ? x[n * 32 + k] : 0.f;
    }
    for (int idx = tid; idx < 128 * 32; idx += NT) {
        int o = idx >> 5, k = idx & 31;
        sW[o * 33 + k] = W[o * 32 + k];
    }
    __syncthreads();
    int tc = tid & 31, trg = tid >> 5;
    float acc[4][4] = {};
#pragma unroll 8
    for (int k = 0; k < 32; k++) {
        float a[4], w[4];
#pragma unroll
        for (int i = 0; i < 4; i++) a[i] = sA[(trg * 4 + i) * 33 + k];
#pragma unroll
        for (int j = 0; j < 4; j++) w[j] = sW[(tc + 32 * j) * 33 + k];
#pragma unroll
        for (int i = 0; i < 4; i++)
#pragma unroll
            for (int j = 0; j < 4; j++) acc[i][j] += a[i] * w[j];
    }
#pragma unroll
    for (int i = 0; i < 4; i++) {
        int n = n0 + trg * 4 + i;
        if (n < NN)
#pragma unroll
            for (int j = 0; j < 4; j++) {
                int c = tc + 32 * j;
                g_h[n * HID + c] = fmaxf(acc[i][j] + b[c], 0.f);
            }
    }
}

// ---------------- attention scores ----------------
// per edge: a = lrelu(W1 @ [hs;hd;ea] + b1), score = W2.a + b2
// block = 256 thr, 32 edges, K=272, hidden=64
__global__ void k_attn(const float* __restrict__ ea,
                       const float* __restrict__ aw1,
                       const float* __restrict__ ab1,
                       const float* __restrict__ aw2,
                       const float* __restrict__ ab2p) {
    __shared__ float sA[32 * 33];
    __shared__ float sW[64 * 33];
    __shared__ int ssrc[32], sdst[32];
    __shared__ float sscore[32];
    int tid = threadIdx.x;
    int e0 = blockIdx.x * 32;
    if (tid < 32) {
        int e = e0 + tid;
        ssrc[tid] = g_src[e];
        sdst[tid] = g_dst[e];
        sscore[tid] = ab2p[0];
    }
    __syncthreads();
    int tc = tid & 31, trg = tid >> 5;
    float acc[4][2] = {};
    for (int kb = 0; kb < 272; kb += 32) {
        int kc = min(32, 272 - kb);
        int tot = 32 * kc;
        for (int idx = tid; idx < tot; idx += NT) {
            int r, kk;
            if (kc == 32) { r = idx >> 5; kk = idx & 31; }
            else          { r = idx >> 4; kk = idx & 15; }
            int kg = kb + kk;
            float v;
            if (kg < 128)      v = g_h[ssrc[r] * HID + kg];
            else if (kg < 256) v = g_h[sdst[r] * HID + kg - 128];
            else               v = ea[(e0 + r) * 16 + kg - 256];
            sA[r * 33 + kk] = v;
        }
        int wtot = 64 * kc;
        for (int idx = tid; idx < wtot; idx += NT) {
            int o, kk;
            if (kc == 32) { o = idx >> 5; kk = idx & 31; }
            else          { o = idx >> 4; kk = idx & 15; }
            sW[o * 33 + kk] = aw1[o * 272 + kb + kk];
        }
        __syncthreads();
#pragma unroll 8
        for (int k = 0; k < kc; k++) {
            float a[4], w[2];
#pragma unroll
            for (int i = 0; i < 4; i++) a[i] = sA[(trg * 4 + i) * 33 + k];
#pragma unroll
            for (int j = 0; j < 2; j++) w[j] = sW[(tc + 32 * j) * 33 + k];
#pragma unroll
            for (int i = 0; i < 4; i++)
#pragma unroll
                for (int j = 0; j < 2; j++) acc[i][j] += a[i] * w[j];
        }
        __syncthreads();
    }
    float p[4] = {0.f, 0.f, 0.f, 0.f};
#pragma unroll
    for (int j = 0; j < 2; j++) {
        int c = tc + 32 * j;
        float b = ab1[c], w2 = aw2[c];
#pragma unroll
        for (int i = 0; i < 4; i++) {
            float v = acc[i][j] + b;
            v = (v > 0.f) ? v : 0.2f * v;  // leaky relu, slope 0.2
            p[i] += v * w2;
        }
    }
#pragma unroll
    for (int i = 0; i < 4; i++) atomicAdd(&sscore[trg * 4 + i], p[i]);
    __syncthreads();
    if (tid < 32) {
        float s = sscore[tid];
        g_scores[e0 + tid] = s;
        float m = s;
#pragma unroll
        for (int off = 16; off > 0; off >>= 1)
            m = fmaxf(m, __shfl_down_sync(0xffffffffu, m, off));
        if (tid == 0) atomicMax(&g_maxenc, fenc(m));
    }
}

// ---------------- exp + scatter sum ----------------
__global__ void k_exp() {
    int i = blockIdx.x * blockDim.x + threadIdx.x;
    if (i >= NE) return;
    float m = fdec(g_maxenc);
    float es = expf(g_scores[i] - m);
    g_es[i] = es;
    atomicAdd(&g_sumexp[g_dst[i]], es);
}

// ---------------- message MLP + weighted scatter ----------------
// msg = (relu([hs;ea] @ W1^T + b1)) @ W2^T + b2 ; agg[dst] += msg * w_e
__global__ void k_msg(const float* __restrict__ ea,
                      const float* __restrict__ mw1,
                      const float* __restrict__ mb1,
                      const float* __restrict__ mw2,
                      const float* __restrict__ mb2) {
    __shared__ float sA[32 * 33];
    __shared__ float sW[128 * 33];
    __shared__ float sM[32 * 129];
    __shared__ int ssrc[32], sdst[32];
    __shared__ float swt[32];
    int tid = threadIdx.x;
    int e0 = blockIdx.x * 32;
    if (tid < 32) {
        int e = e0 + tid;
        ssrc[tid] = g_src[e];
        int d = g_dst[e];
        sdst[tid] = d;
        swt[tid] = g_es[e] / (g_sumexp[d] + 1e-6f);
    }
    __syncthreads();
    int tc = tid & 31, trg = tid >> 5;
    float acc[4][4] = {};
    for (int kb = 0; kb < 144; kb += 32) {
        int kc = min(32, 144 - kb);
        int tot = 32 * kc;
        for (int idx = tid; idx < tot; idx += NT) {
            int r, kk;
            if (kc == 32) { r = idx >> 5; kk = idx & 31; }
            else          { r = idx >> 4; kk = idx & 15; }
            int kg = kb + kk;
            float v = (kg < 128) ? g_h[ssrc[r] * HID + kg]
                                 : ea[(e0 + r) * 16 + kg - 128];
            sA[r * 33 + kk] = v;
        }
        int wtot = 128 * kc;
        for (int idx = tid; idx < wtot; idx += NT) {
            int o, kk;
            if (kc == 32) { o = idx >> 5; kk = idx & 31; }
            else          { o = idx >> 4; kk = idx & 15; }
            sW[o * 33 + kk] = mw1[o * 144 + kb + kk];
        }
        __syncthreads();
#pragma unroll 8
        for (int k = 0; k < kc; k++) {
            float a[4], w[4];
#pragma unroll
            for (int i = 0; i < 4; i++) a[i] = sA[(trg * 4 + i) * 33 + k];
#pragma unroll
            for (int j = 0; j < 4; j++) w[j] = sW[(tc + 32 * j) * 33 + k];
#pragma unroll
            for (int i = 0; i < 4; i++)
#pragma unroll
                for (int j = 0; j < 4; j++) acc[i][j] += a[i] * w[j];
        }
        __syncthreads();
    }
#pragma unroll
    for (int i = 0; i < 4; i++)
#pragma unroll
        for (int j = 0; j < 4; j++) {
            int c = tc + 32 * j;
            sM[(trg * 4 + i) * 129 + c] = fmaxf(acc[i][j] + mb1[c], 0.f);
        }
    __syncthreads();
    float acc2[4][4] = {};
    for (int kb = 0; kb < 128; kb += 32) {
        for (int idx = tid; idx < 128 * 32; idx += NT) {
            int o = idx >> 5, kk = idx & 31;
            sW[o * 33 + kk] = mw2[o * 128 + kb + kk];
        }
        __syncthreads();
#pragma unroll 8
        for (int k = 0; k < 32; k++) {
            float a[4], w[4];
#pragma unroll
            for (int i = 0; i < 4; i++) a[i] = sM[(trg * 4 + i) * 129 + kb + k];
#pragma unroll
            for (int j = 0; j < 4; j++) w[j] = sW[(tc + 32 * j) * 33 + k];
#pragma unroll
            for (int i = 0; i < 4; i++)
#pragma unroll
                for (int j = 0; j < 4; j++) acc2[i][j] += a[i] * w[j];
        }
        __syncthreads();
    }
#pragma unroll
    for (int i = 0; i < 4; i++) {
        int r = trg * 4 + i;
        int base = sdst[r] * HID;
        float w = swt[r];
#pragma unroll
        for (int j = 0; j < 4; j++) {
            int c = tc + 32 * j;
            atomicAdd(&g_agg[base + c], (acc2[i][j] + mb2[c]) * w);
        }
    }
}

// ---------------- node update + residual + layernorm ----------------
__global__ void k_update(const float* __restrict__ uw1,
                         const float* __restrict__ ub1,
                         const float* __restrict__ uw2,
                         const float* __restrict__ ub2,
                         const float* __restrict__ lng,
                         const float* __restrict__ lnb) {
    __shared__ float sA[32 * 33];
    __shared__ float sW[128 * 33];
    __shared__ float sM[32 * 129];  // also reused as the output tile for LN
    __shared__ float smu[32], srs[32];
    int tid = threadIdx.x;
    int n0 = blockIdx.x * 32;
    int tc = tid & 31, trg = tid >> 5;
    float acc[4][4] = {};
    for (int kb = 0; kb < 256; kb += 32) {
        for (int idx = tid; idx < 32 * 32; idx += NT) {
            int r = idx >> 5, kk = idx & 31;
            int n = n0 + r;
            int kg = kb + kk;
            float v = 0.f;
            if (n < NN)
                v = (kg < 128) ? g_h[n * HID + kg] : g_agg[n * HID + kg - 128];
            sA[r * 33 + kk] = v;
        }
        for (int idx = tid; idx < 128 * 32; idx += NT) {
            int o = idx >> 5, kk = idx & 31;
            sW[o * 33 + kk] = uw1[o * 256 + kb + kk];
        }
        __syncthreads();
#pragma unroll 8
        for (int k = 0; k < 32; k++) {
            float a[4], w[4];
#pragma unroll
            for (int i = 0; i < 4; i++) a[i] = sA[(trg * 4 + i) * 33 + k];
#pragma unroll
            for (int j = 0; j < 4; j++) w[j] = sW[(tc + 32 * j) * 33 + k];
#pragma unroll
            for (int i = 0; i < 4; i++)
#pragma unroll
                for (int j = 0; j < 4; j++) acc[i][j] += a[i] * w[j];
        }
        __syncthreads();
    }
#pragma unroll
    for (int i = 0; i < 4; i++)
#pragma unroll
        for (int j = 0; j < 4; j++) {
            int c = tc + 32 * j;
            sM[(trg * 4 + i) * 129 + c] = fmaxf(acc[i][j] + ub1[c], 0.f);
        }
    __syncthreads();
    float acc2[4][4] = {};
    for (int kb = 0; kb < 128; kb += 32) {
        for (int idx = tid; idx < 128 * 32; idx += NT) {
            int o = idx >> 5, kk = idx & 31;
            sW[o * 33 + kk] = uw2[o * 128 + kb + kk];
        }
        __syncthreads();
#pragma unroll 8
        for (int k = 0; k < 32; k++) {
            float a[4], w[4];
#pragma unroll
            for (int i = 0; i < 4; i++) a[i] = sM[(trg * 4 + i) * 129 + kb + k];
#pragma unroll
            for (int j = 0; j < 4; j++) w[j] = sW[(tc + 32 * j) * 33 + k];
#pragma unroll
            for (int i = 0; i < 4; i++)
#pragma unroll
                for (int j = 0; j < 4; j++) acc2[i][j] += a[i] * w[j];
        }
        __syncthreads();
    }
    // residual + relu into sM (GEMM2 reads done; last sync above protects reuse)
#pragma unroll
    for (int i = 0; i < 4; i++) {
        int r = trg * 4 + i;
        int n = n0 + r;
        float hv;
#pragma unroll
        for (int j = 0; j < 4; j++) {
            int c = tc + 32 * j;
            hv = (n < NN) ? g_h[n * HID + c] : 0.f;
            float v = acc2[i][j] + ub2[c] + hv;
            sM[r * 129 + c] = fmaxf(v, 0.f);
        }
    }
    __syncthreads();
    if (tid < 32) {
        float s = 0.f;
        for (int c = 0; c < 128; c++) s += sM[tid * 129 + c];
        float mu = s * (1.f / 128.f);
        float v2 = 0.f;
        for (int c = 0; c < 128; c++) {
            float d = sM[tid * 129 + c] - mu;
            v2 += d * d;
        }
        smu[tid] = mu;
        srs[tid] = rsqrtf(v2 * (1.f / 128.f) + 1e-5f);
    }
    __syncthreads();
#pragma unroll
    for (int i = 0; i < 4; i++) {
        int r = trg * 4 + i;
        int n = n0 + r;
        if (n < NN)
#pragma unroll
            for (int j = 0; j < 4; j++) {
                int c = tc + 32 * j;
                float v = (sM[r * 129 + c] - smu[r]) * srs[r] * lng[c] + lnb[c];
                g_h[n * HID + c] = v;
            }
    }
}

// ---------------- final readout ----------------
// q = relu([h;ctx] @ W1^T + b1) @ W2^T + b2
__global__ void k_final(const float* __restrict__ gc,
                        const float* __restrict__ qw1,
                        const float* __restrict__ qb1,
                        const float* __restrict__ qw2,
                        const float* __restrict__ qb2p,
                        float* __restrict__ out) {
    __shared__ float sA[32 * 33];
    __shared__ float sW[128 * 33];
    __shared__ float sctx[64];
    __shared__ float sout[32];
    int tid = threadIdx.x;
    int n0 = blockIdx.x * 32;
    if (tid < 64) sctx[tid] = gc[tid];
    if (tid < 32) sout[tid] = qb2p[0];
    __syncthreads();
    int tc = tid & 31, trg = tid >> 5;
    float acc[4][4] = {};
    for (int kb = 0; kb < 192; kb += 32) {
        for (int idx = tid; idx < 32 * 32; idx += NT) {
            int r = idx >> 5, kk = idx & 31;
            int n = n0 + r;
            int kg = kb + kk;
            float v = 0.f;
            if (n < NN) v = (kg < 128) ? g_h[n * HID + kg] : sctx[kg - 128];
            sA[r * 33 + kk] = v;
        }
        for (int idx = tid; idx < 128 * 32; idx += NT) {
            int o = idx >> 5, kk = idx & 31;
            sW[o * 33 + kk] = qw1[o * 192 + kb + kk];
        }
        __syncthreads();
#pragma unroll 8
        for (int k = 0; k < 32; k++) {
            float a[4], w[4];
#pragma unroll
            for (int i = 0; i < 4; i++) a[i] = sA[(trg * 4 + i) * 33 + k];
#pragma unroll
            for (int j = 0; j < 4; j++) w[j] = sW[(tc + 32 * j) * 33 + k];
#pragma unroll
            for (int i = 0; i < 4; i++)
#pragma unroll
                for (int j = 0; j < 4; j++) acc[i][j] += a[i] * w[j];
        }
        __syncthreads();
    }
    float p[4] = {0.f, 0.f, 0.f, 0.f};
#pragma unroll
    for (int j = 0; j < 4; j++) {
        int c = tc + 32 * j;
        float b = qb1[c], w2 = qw2[c];
#pragma unroll
        for (int i = 0; i < 4; i++) {
            float v = fmaxf(acc[i][j] + b, 0.f);
            p[i] += v * w2;
        }
    }
#pragma unroll
    for (int i = 0; i < 4; i++) atomicAdd(&sout[trg * 4 + i], p[i]);
    __syncthreads();
    if (tid < 32) {
        int n = n0 + tid;
        if (n < NN) out[n] = sout[tid];
    }
}

// ---------------- launch ----------------
extern "C" void kernel_launch(void* const* d_in, const int* in_sizes, int n_in,
                              void* d_out, int out_size) {
    const float* x    = (const float*)d_in[0];
    const void*  eidx = d_in[1];
    const float* ea   = (const float*)d_in[2];
    const float* gc   = (const float*)d_in[3];
    const float* npw  = (const float*)d_in[4];
    const float* npb  = (const float*)d_in[5];
    const float* mw1  = (const float*)d_in[6];
    const float* mb1  = (const float*)d_in[7];
    const float* mw2  = (const float*)d_in[8];
    const float* mb2  = (const float*)d_in[9];
    const float* aw1  = (const float*)d_in[10];
    const float* ab1  = (const float*)d_in[11];
    const float* aw2  = (const float*)d_in[12];
    const float* ab2  = (const float*)d_in[13];
    const float* uw1  = (const float*)d_in[14];
    const float* ub1  = (const float*)d_in[15];
    const float* uw2  = (const float*)d_in[16];
    const float* ub2  = (const float*)d_in[17];
    const float* lng  = (const float*)d_in[18];
    const float* lnb  = (const float*)d_in[19];
    const float* qw1  = (const float*)d_in[20];
    const float* qb1  = (const float*)d_in[21];
    const float* qw2  = (const float*)d_in[22];
    const float* qb2  = (const float*)d_in[23];
    float* out = (float*)d_out;

    k_detect<<<1, NT>>>((const unsigned*)eidx);
    k_convert<<<(NE + NT - 1) / NT, NT>>>(eidx);
    k_nodeproj<<<(NN + 31) / 32, NT>>>(x, npw, npb);

    for (int l = 0; l < 3; l++) {
        k_reset<<<1024, NT>>>();
        k_attn<<<NE / 32, NT>>>(ea, aw1 + l * 64 * 272, ab1 + l * 64,
                                aw2 + l * 64, ab2 + l);
        k_exp<<<(NE + NT - 1) / NT, NT>>>();
        k_msg<<<NE / 32, NT>>>(ea, mw1 + l * 128 * 144, mb1 + l * 128,
                               mw2 + l * 128 * 128, mb2 + l * 128);
        k_update<<<(NN + 31) / 32, NT>>>(uw1 + l * 128 * 256, ub1 + l * 128,
                                         uw2 + l * 128 * 128, ub2 + l * 128,
                                         lng + l * 128, lnb + l * 128);
    }
    k_final<<<(NN + 31) / 32, NT>>>(gc, qw1, qb1, qw2, qb2, out);
}

// round 2
// speedup vs baseline: 1.3157x; 1.3157x over previous
#include <cuda_runtime.h>

#define NN 50000
#define NE 600000
#define HID 128
#define NT 256

typedef unsigned long long u64;

// ---------------- scratch (device globals; no allocation) ----------------
__device__ float g_h[NN * HID];
__device__ float g_agg[NN * HID];
__device__ float g_sumexp[NN];
__device__ float g_scores[NE];
__device__ float g_es[NE];
__device__ int   g_src[NE];
__device__ int   g_dst[NE];
__device__ unsigned g_maxenc;
__device__ int   g_is64;

__device__ __forceinline__ unsigned fenc(float f) {
    unsigned u = __float_as_uint(f);
    return (u & 0x80000000u) ? ~u : (u | 0x80000000u);
}
__device__ __forceinline__ float fdec(unsigned u) {
    return (u & 0x80000000u) ? __uint_as_float(u & 0x7fffffffu)
                             : __uint_as_float(~u);
}

// ---------------- packed f32x2 helpers ----------------
__device__ __forceinline__ u64 pack2(float lo, float hi) {
    u64 r;
    asm("mov.b64 %0, {%1, %2};" : "=l"(r)
        : "r"(__float_as_uint(lo)), "r"(__float_as_uint(hi)));
    return r;
}
__device__ __forceinline__ u64 pack2s(float v) { return pack2(v, v); }
__device__ __forceinline__ void ffma2(u64 &d, u64 a, u64 b) {
    asm("fma.rn.f32x2 %0, %1, %2, %0;" : "+l"(d) : "l"(a), "l"(b));
}
__device__ __forceinline__ void unpack2(u64 v, float &lo, float &hi) {
    unsigned a, b;
    asm("mov.b64 {%0, %1}, %2;" : "=r"(a), "=r"(b) : "l"(v));
    lo = __uint_as_float(a);
    hi = __uint_as_float(b);
}

// ---------------- dtype detection + index conversion ----------------
__global__ void k_detect(const unsigned* __restrict__ raw) {
    __shared__ int nz;
    if (threadIdx.x == 0) nz = 0;
    __syncthreads();
    for (int i = threadIdx.x; i < 2048; i += NT)
        if (raw[2 * i + 1] != 0u) atomicOr(&nz, 1);
    __syncthreads();
    if (threadIdx.x == 0) g_is64 = (nz == 0) ? 1 : 0;
}

__global__ void k_convert(const void* __restrict__ eidx) {
    int i = blockIdx.x * blockDim.x + threadIdx.x;
    if (i >= NE) return;
    if (g_is64) {
        const long long* p = (const long long*)eidx;
        g_src[i] = (int)p[i];
        g_dst[i] = (int)p[NE + i];
    } else {
        const int* p = (const int*)eidx;
        g_src[i] = p[i];
        g_dst[i] = p[NE + i];
    }
}

// ---------------- per-layer reset ----------------
__global__ void k_reset() {
    long long tot = (long long)NN * HID;
    long long stride = (long long)gridDim.x * blockDim.x;
    long long i0 = (long long)blockIdx.x * blockDim.x + threadIdx.x;
    for (long long i = i0; i < tot; i += stride) {
        g_agg[i] = 0.f;
        if (i < NN) g_sumexp[i] = 0.f;
    }
    if (i0 == 0) g_maxenc = 0x007FFFFFu;
}

// ---------------- node projection (fp32 scalar; tiny) ----------------
__global__ void k_nodeproj(const float* __restrict__ x,
                           const float* __restrict__ W,
                           const float* __restrict__ b) {
    __shared__ float sA[32 * 33];
    __shared__ float sW[128 * 33];
    int tid = threadIdx.x;
    int n0 = blockIdx.x * 32;
    for (int idx = tid; idx < 32 * 32; idx += NT) {
        int r = idx >> 5, k = idx & 31;
        int n = n0 + r;
        sA[r * 33 + k] = (n < NN) ? x[n * 32 + k] : 0.f;
    }
    for (int idx = tid; idx < 128 * 32; idx += NT) {
        int o = idx >> 5, k = idx & 31;
        sW[o * 33 + k] = W[o * 32 + k];
    }
    __syncthreads();
    int tc = tid & 31, trg = tid >> 5;
    float acc[4][4] = {};
#pragma unroll 8
    for (int k = 0; k < 32; k++) {
        float a[4], w[4];
#pragma unroll
        for (int i = 0; i < 4; i++) a[i] = sA[(trg * 4 + i) * 33 + k];
#pragma unroll
        for (int j = 0; j < 4; j++) w[j] = sW[(tc + 32 * j) * 33 + k];
#pragma unroll
        for (int i = 0; i < 4; i++)
#pragma unroll
            for (int j = 0; j < 4; j++) acc[i][j] += a[i] * w[j];
    }
#pragma unroll
    for (int i = 0; i < 4; i++) {
        int n = n0 + trg * 4 + i;
        if (n < NN)
#pragma unroll
            for (int j = 0; j < 4; j++) {
                int c = tc + 32 * j;
                g_h[n * HID + c] = fmaxf(acc[i][j] + b[c], 0.f);
            }
    }
}

// ---------------- attention scores (FFMA2, 256 edges x 64 cols) ----------------
__global__ void __launch_bounds__(256, 2)
k_attn(const float* __restrict__ ea,
       const float* __restrict__ aw1,
       const float* __restrict__ ab1,
       const float* __restrict__ aw2,
       const float* __restrict__ ab2p) {
    __shared__ float sAT[16 * 260];
    __shared__ float sW[16 * 64];
    __shared__ int ssrc[256], sdst[256];
    __shared__ unsigned smax;
    int tid = threadIdx.x;
    int e0 = blockIdx.x * 256;
    {
        int e = e0 + tid;
        if (e < NE) { ssrc[tid] = g_src[e]; sdst[tid] = g_dst[e]; }
        else        { ssrc[tid] = 0;        sdst[tid] = 0; }
    }
    if (tid == 0) smax = 0x007FFFFFu;
    __syncthreads();

    int tcol = tid & 7, trow = tid >> 3;
    int r0 = trow * 8, c0 = tcol * 8;

    u64 acc[8][4];
#pragma unroll
    for (int i = 0; i < 8; i++)
#pragma unroll
        for (int j = 0; j < 4; j++) acc[i][j] = 0ull;

    int wo = tid & 63, wkq = tid >> 6;  // weight loader

    for (int kb = 0; kb < 272; kb += 16) {
        // A tile (gathered, k-major)
#pragma unroll
        for (int kq = 0; kq < 4; kq++) {
            int kg = kb + kq * 4;
            float4 v;
            if (kg < 128) {
                v = *(const float4*)&g_h[ssrc[tid] * HID + kg];
            } else if (kg < 256) {
                v = *(const float4*)&g_h[sdst[tid] * HID + (kg - 128)];
            } else {
                if (e0 + tid < NE)
                    v = *(const float4*)&ea[(e0 + tid) * 16 + (kg - 256)];
                else
                    v = make_float4(0.f, 0.f, 0.f, 0.f);
            }
            sAT[(kq * 4 + 0) * 260 + tid] = v.x;
            sAT[(kq * 4 + 1) * 260 + tid] = v.y;
            sAT[(kq * 4 + 2) * 260 + tid] = v.z;
            sAT[(kq * 4 + 3) * 260 + tid] = v.w;
        }
        // W tile (k-major)
        {
            float4 w = *(const float4*)&aw1[wo * 272 + kb + wkq * 4];
            sW[(wkq * 4 + 0) * 64 + wo] = w.x;
            sW[(wkq * 4 + 1) * 64 + wo] = w.y;
            sW[(wkq * 4 + 2) * 64 + wo] = w.z;
            sW[(wkq * 4 + 3) * 64 + wo] = w.w;
        }
        __syncthreads();
#pragma unroll
        for (int k = 0; k < 16; k++) {
            float4 a0 = *(const float4*)&sAT[k * 260 + r0];
            float4 a1 = *(const float4*)&sAT[k * 260 + r0 + 4];
            float4 w0 = *(const float4*)&sW[k * 64 + c0];
            float4 w1 = *(const float4*)&sW[k * 64 + c0 + 4];
            u64 ww0 = pack2(w0.x, w0.y), ww1 = pack2(w0.z, w0.w);
            u64 ww2 = pack2(w1.x, w1.y), ww3 = pack2(w1.z, w1.w);
            float av[8] = {a0.x, a0.y, a0.z, a0.w, a1.x, a1.y, a1.z, a1.w};
#pragma unroll
            for (int i = 0; i < 8; i++) {
                u64 ap = pack2s(av[i]);
                ffma2(acc[i][0], ap, ww0);
                ffma2(acc[i][1], ap, ww1);
                ffma2(acc[i][2], ap, ww2);
                ffma2(acc[i][3], ap, ww3);
            }
        }
        __syncthreads();
    }

    // epilogue: bias + leaky-relu + dot with aw2, reduce over 8 col-threads
    float4 b0 = *(const float4*)&ab1[c0];
    float4 b1 = *(const float4*)&ab1[c0 + 4];
    float4 v0 = *(const float4*)&aw2[c0];
    float4 v1 = *(const float4*)&aw2[c0 + 4];
    float bb[8] = {b0.x, b0.y, b0.z, b0.w, b1.x, b1.y, b1.z, b1.w};
    float vv[8] = {v0.x, v0.y, v0.z, v0.w, v1.x, v1.y, v1.z, v1.w};
    float b2 = ab2p[0];
    float mloc = -3.4e38f;
    float ps[8];
#pragma unroll
    for (int i = 0; i < 8; i++) {
        float p = 0.f;
#pragma unroll
        for (int jp = 0; jp < 4; jp++) {
            float lo, hi;
            unpack2(acc[i][jp], lo, hi);
            float x0 = lo + bb[2 * jp];
            float x1 = hi + bb[2 * jp + 1];
            x0 = (x0 > 0.f) ? x0 : 0.2f * x0;
            x1 = (x1 > 0.f) ? x1 : 0.2f * x1;
            p += x0 * vv[2 * jp] + x1 * vv[2 * jp + 1];
        }
#pragma unroll
        for (int off = 4; off > 0; off >>= 1)
            p += __shfl_xor_sync(0xffffffffu, p, off);
        ps[i] = p + b2;
    }
    if (tcol == 0) {
#pragma unroll
        for (int i = 0; i < 8; i++) {
            int e = e0 + r0 + i;
            if (e < NE) {
                g_scores[e] = ps[i];
                mloc = fmaxf(mloc, ps[i]);
            }
        }
        atomicMax(&smax, fenc(mloc));
    }
    __syncthreads();
    if (tid == 0) atomicMax(&g_maxenc, smax);
}

// ---------------- exp + scatter sum ----------------
__global__ void k_exp() {
    int i = blockIdx.x * blockDim.x + threadIdx.x;
    if (i >= NE) return;
    float m = fdec(g_maxenc);
    float es = expf(g_scores[i] - m);
    g_es[i] = es;
    atomicAdd(&g_sumexp[g_dst[i]], es);
}

// ---------------- message MLP + weighted scatter (FFMA2, 128x128) ----------------
__global__ void __launch_bounds__(256, 2)
k_msg(const float* __restrict__ ea,
      const float* __restrict__ mw1,
      const float* __restrict__ mb1,
      const float* __restrict__ mw2,
      const float* __restrict__ mb2) {
    extern __shared__ float sm[];
    float* sAT = sm;                      // 16 x 132
    float* sW  = sAT + 16 * 132;          // 16 x 128
    float* sM  = sW + 16 * 128;           // 128 x 132 (row-major)
    int*   ssrc = (int*)(sM + 128 * 132);
    int*   sdst = ssrc + 128;
    float* swt  = (float*)(sdst + 128);

    int tid = threadIdx.x;
    int e0 = blockIdx.x * 128;
    if (tid < 128) {
        int e = e0 + tid;
        if (e < NE) {
            ssrc[tid] = g_src[e];
            int d = g_dst[e];
            sdst[tid] = d;
            swt[tid] = g_es[e] / (g_sumexp[d] + 1e-6f);
        } else {
            ssrc[tid] = 0; sdst[tid] = 0; swt[tid] = 0.f;
        }
    }
    __syncthreads();

    int tcol = tid & 15, trow = tid >> 4;
    int r0 = trow * 8, c0 = tcol * 8;
    int lrow = tid & 127;
    int lkq0 = (tid >> 7) * 2;

    u64 acc[8][4];
#pragma unroll
    for (int i = 0; i < 8; i++)
#pragma unroll
        for (int j = 0; j < 4; j++) acc[i][j] = 0ull;

    for (int kb = 0; kb < 144; kb += 16) {
#pragma unroll
        for (int q = 0; q < 2; q++) {
            int kq = lkq0 + q;
            int kg = kb + kq * 4;
            float4 v;
            if (kg < 128) {
                v = *(const float4*)&g_h[ssrc[lrow] * HID + kg];
            } else {
                if (e0 + lrow < NE)
                    v = *(const float4*)&ea[(e0 + lrow) * 16 + (kg - 128)];
                else
                    v = make_float4(0.f, 0.f, 0.f, 0.f);
            }
            sAT[(kq * 4 + 0) * 132 + lrow] = v.x;
            sAT[(kq * 4 + 1) * 132 + lrow] = v.y;
            sAT[(kq * 4 + 2) * 132 + lrow] = v.z;
            sAT[(kq * 4 + 3) * 132 + lrow] = v.w;
        }
#pragma unroll
        for (int q = 0; q < 2; q++) {
            int kq = lkq0 + q;
            float4 w = *(const float4*)&mw1[lrow * 144 + kb + kq * 4];
            sW[(kq * 4 + 0) * 128 + lrow] = w.x;
            sW[(kq * 4 + 1) * 128 + lrow] = w.y;
            sW[(kq * 4 + 2) * 128 + lrow] = w.z;
            sW[(kq * 4 + 3) * 128 + lrow] = w.w;
        }
        __syncthreads();
#pragma unroll
        for (int k = 0; k < 16; k++) {
            float4 a0 = *(const float4*)&sAT[k * 132 + r0];
            float4 a1 = *(const float4*)&sAT[k * 132 + r0 + 4];
            float4 w0 = *(const float4*)&sW[k * 128 + c0];
            float4 w1 = *(const float4*)&sW[k * 128 + c0 + 4];
            u64 ww0 = pack2(w0.x, w0.y), ww1 = pack2(w0.z, w0.w);
            u64 ww2 = pack2(w1.x, w1.y), ww3 = pack2(w1.z, w1.w);
            float av[8] = {a0.x, a0.y, a0.z, a0.w, a1.x, a1.y, a1.z, a1.w};
#pragma unroll
            for (int i = 0; i < 8; i++) {
                u64 ap = pack2s(av[i]);
                ffma2(acc[i][0], ap, ww0);
                ffma2(acc[i][1], ap, ww1);
                ffma2(acc[i][2], ap, ww2);
                ffma2(acc[i][3], ap, ww3);
            }
        }
        __syncthreads();
    }

    // epilogue1: bias + relu -> sM row-major
    {
        float4 b0 = *(const float4*)&mb1[c0];
        float4 b1 = *(const float4*)&mb1[c0 + 4];
        float bb[8] = {b0.x, b0.y, b0.z, b0.w, b1.x, b1.y, b1.z, b1.w};
#pragma unroll
        for (int i = 0; i < 8; i++) {
            float* row = &sM[(r0 + i) * 132 + c0];
#pragma unroll
            for (int jp = 0; jp < 4; jp++) {
                float lo, hi;
                unpack2(acc[i][jp], lo, hi);
                row[2 * jp]     = fmaxf(lo + bb[2 * jp], 0.f);
                row[2 * jp + 1] = fmaxf(hi + bb[2 * jp + 1], 0.f);
            }
        }
    }
    __syncthreads();

    // GEMM2 over sM (K=128)
    u64 acc2[8][4];
#pragma unroll
    for (int i = 0; i < 8; i++)
#pragma unroll
        for (int j = 0; j < 4; j++) acc2[i][j] = 0ull;

    for (int kb = 0; kb < 128; kb += 16) {
#pragma unroll
        for (int q = 0; q < 2; q++) {
            int kq = lkq0 + q;
            float4 w = *(const float4*)&mw2[lrow * 128 + kb + kq * 4];
            sW[(kq * 4 + 0) * 128 + lrow] = w.x;
            sW[(kq * 4 + 1) * 128 + lrow] = w.y;
            sW[(kq * 4 + 2) * 128 + lrow] = w.z;
            sW[(kq * 4 + 3) * 128 + lrow] = w.w;
        }
        __syncthreads();
#pragma unroll
        for (int k = 0; k < 16; k++) {
            int kg = kb + k;
            float4 w0 = *(const float4*)&sW[k * 128 + c0];
            float4 w1 = *(const float4*)&sW[k * 128 + c0 + 4];
            u64 ww0 = pack2(w0.x, w0.y), ww1 = pack2(w0.z, w0.w);
            u64 ww2 = pack2(w1.x, w1.y), ww3 = pack2(w1.z, w1.w);
#pragma unroll
            for (int i = 0; i < 8; i++) {
                u64 ap = pack2s(sM[(r0 + i) * 132 + kg]);
                ffma2(acc2[i][0], ap, ww0);
                ffma2(acc2[i][1], ap, ww1);
                ffma2(acc2[i][2], ap, ww2);
                ffma2(acc2[i][3], ap, ww3);
            }
        }
        __syncthreads();
    }

    // epilogue2: bias, weight, atomic scatter
    {
        float4 b0 = *(const float4*)&mb2[c0];
        float4 b1 = *(const float4*)&mb2[c0 + 4];
        float bb[8] = {b0.x, b0.y, b0.z, b0.w, b1.x, b1.y, b1.z, b1.w};
#pragma unroll
        for (int i = 0; i < 8; i++) {
            int r = r0 + i;
            int e = e0 + r;
            if (e < NE) {
                float w = swt[r];
                float* dp = &g_agg[sdst[r] * HID + c0];
#pragma unroll
                for (int jp = 0; jp < 4; jp++) {
                    float lo, hi;
                    unpack2(acc2[i][jp], lo, hi);
                    atomicAdd(&dp[2 * jp],     (lo + bb[2 * jp]) * w);
                    atomicAdd(&dp[2 * jp + 1], (hi + bb[2 * jp + 1]) * w);
                }
            }
        }
    }
}

// ---------------- node update + residual + layernorm (FFMA2, 128x128) ----------------
__global__ void __launch_bounds__(256, 2)
k_update(const float* __restrict__ uw1,
         const float* __restrict__ ub1,
         const float* __restrict__ uw2,
         const float* __restrict__ ub2,
         const float* __restrict__ lng,
         const float* __restrict__ lnb) {
    extern __shared__ float sm[];
    float* sAT = sm;                  // 16 x 132
    float* sW  = sAT + 16 * 132;      // 16 x 128
    float* sM  = sW + 16 * 128;       // 128 x 132

    int tid = threadIdx.x;
    int n0 = blockIdx.x * 128;
    int tcol = tid & 15, trow = tid >> 4;
    int r0 = trow * 8, c0 = tcol * 8;
    int lrow = tid & 127;
    int lkq0 = (tid >> 7) * 2;

    u64 acc[8][4];
#pragma unroll
    for (int i = 0; i < 8; i++)
#pragma unroll
        for (int j = 0; j < 4; j++) acc[i][j] = 0ull;

    for (int kb = 0; kb < 256; kb += 16) {
#pragma unroll
        for (int q = 0; q < 2; q++) {
            int kq = lkq0 + q;
            int kg = kb + kq * 4;
            int n = n0 + lrow;
            float4 v = make_float4(0.f, 0.f, 0.f, 0.f);
            if (n < NN) {
                if (kg < 128) v = *(const float4*)&g_h[n * HID + kg];
                else          v = *(const float4*)&g_agg[n * HID + (kg - 128)];
            }
            sAT[(kq * 4 + 0) * 132 + lrow] = v.x;
            sAT[(kq * 4 + 1) * 132 + lrow] = v.y;
            sAT[(kq * 4 + 2) * 132 + lrow] = v.z;
            sAT[(kq * 4 + 3) * 132 + lrow] = v.w;
        }
#pragma unroll
        for (int q = 0; q < 2; q++) {
            int kq = lkq0 + q;
            float4 w = *(const float4*)&uw1[lrow * 256 + kb + kq * 4];
            sW[(kq * 4 + 0) * 128 + lrow] = w.x;
            sW[(kq * 4 + 1) * 128 + lrow] = w.y;
            sW[(kq * 4 + 2) * 128 + lrow] = w.z;
            sW[(kq * 4 + 3) * 128 + lrow] = w.w;
        }
        __syncthreads();
#pragma unroll
        for (int k = 0; k < 16; k++) {
            float4 a0 = *(const float4*)&sAT[k * 132 + r0];
            float4 a1 = *(const float4*)&sAT[k * 132 + r0 + 4];
            float4 w0 = *(const float4*)&sW[k * 128 + c0];
            float4 w1 = *(const float4*)&sW[k * 128 + c0 + 4];
            u64 ww0 = pack2(w0.x, w0.y), ww1 = pack2(w0.z, w0.w);
            u64 ww2 = pack2(w1.x, w1.y), ww3 = pack2(w1.z, w1.w);
            float av[8] = {a0.x, a0.y, a0.z, a0.w, a1.x, a1.y, a1.z, a1.w};
#pragma unroll
            for (int i = 0; i < 8; i++) {
                u64 ap = pack2s(av[i]);
                ffma2(acc[i][0], ap, ww0);
                ffma2(acc[i][1], ap, ww1);
                ffma2(acc[i][2], ap, ww2);
                ffma2(acc[i][3], ap, ww3);
            }
        }
        __syncthreads();
    }

    {
        float4 b0 = *(const float4*)&ub1[c0];
        float4 b1 = *(const float4*)&ub1[c0 + 4];
        float bb[8] = {b0.x, b0.y, b0.z, b0.w, b1.x, b1.y, b1.z, b1.w};
#pragma unroll
        for (int i = 0; i < 8; i++) {
            float* row = &sM[(r0 + i) * 132 + c0];
#pragma unroll
            for (int jp = 0; jp < 4; jp++) {
                float lo, hi;
                unpack2(acc[i][jp], lo, hi);
                row[2 * jp]     = fmaxf(lo + bb[2 * jp], 0.f);
                row[2 * jp + 1] = fmaxf(hi + bb[2 * jp + 1], 0.f);
            }
        }
    }
    __syncthreads();

    u64 acc2[8][4];
#pragma unroll
    for (int i = 0; i < 8; i++)
#pragma unroll
        for (int j = 0; j < 4; j++) acc2[i][j] = 0ull;

    for (int kb = 0; kb < 128; kb += 16) {
#pragma unroll
        for (int q = 0; q < 2; q++) {
            int kq = lkq0 + q;
            float4 w = *(const float4*)&uw2[lrow * 128 + kb + kq * 4];
            sW[(kq * 4 + 0) * 128 + lrow] = w.x;
            sW[(kq * 4 + 1) * 128 + lrow] = w.y;
            sW[(kq * 4 + 2) * 128 + lrow] = w.z;
            sW[(kq * 4 + 3) * 128 + lrow] = w.w;
        }
        __syncthreads();
#pragma unroll
        for (int k = 0; k < 16; k++) {
            int kg = kb + k;
            float4 w0 = *(const float4*)&sW[k * 128 + c0];
            float4 w1 = *(const float4*)&sW[k * 128 + c0 + 4];
            u64 ww0 = pack2(w0.x, w0.y), ww1 = pack2(w0.z, w0.w);
            u64 ww2 = pack2(w1.x, w1.y), ww3 = pack2(w1.z, w1.w);
#pragma unroll
            for (int i = 0; i < 8; i++) {
                u64 ap = pack2s(sM[(r0 + i) * 132 + kg]);
                ffma2(acc2[i][0], ap, ww0);
                ffma2(acc2[i][1], ap, ww1);
                ffma2(acc2[i][2], ap, ww2);
                ffma2(acc2[i][3], ap, ww3);
            }
        }
        __syncthreads();
    }

    // epilogue: + bias + residual, relu, layernorm in registers
    {
        float4 b0 = *(const float4*)&ub2[c0];
        float4 b1 = *(const float4*)&ub2[c0 + 4];
        float bb[8] = {b0.x, b0.y, b0.z, b0.w, b1.x, b1.y, b1.z, b1.w};
        float4 g0 = *(const float4*)&lng[c0];
        float4 g1 = *(const float4*)&lng[c0 + 4];
        float gg[8] = {g0.x, g0.y, g0.z, g0.w, g1.x, g1.y, g1.z, g1.w};
        float4 q0 = *(const float4*)&lnb[c0];
        float4 q1 = *(const float4*)&lnb[c0 + 4];
        float qq[8] = {q0.x, q0.y, q0.z, q0.w, q1.x, q1.y, q1.z, q1.w};

#pragma unroll
        for (int i = 0; i < 8; i++) {
            int n = n0 + r0 + i;
            float v[8];
            if (n < NN) {
                float4 h0 = *(const float4*)&g_h[n * HID + c0];
                float4 h1 = *(const float4*)&g_h[n * HID + c0 + 4];
                float hh[8] = {h0.x, h0.y, h0.z, h0.w, h1.x, h1.y, h1.z, h1.w};
#pragma unroll
                for (int jp = 0; jp < 4; jp++) {
                    float lo, hi;
                    unpack2(acc2[i][jp], lo, hi);
                    v[2 * jp]     = fmaxf(lo + bb[2 * jp] + hh[2 * jp], 0.f);
                    v[2 * jp + 1] = fmaxf(hi + bb[2 * jp + 1] + hh[2 * jp + 1], 0.f);
                }
            } else {
#pragma unroll
                for (int j = 0; j < 8; j++) v[j] = 0.f;
            }
            float s = 0.f, sq = 0.f;
#pragma unroll
            for (int j = 0; j < 8; j++) { s += v[j]; sq += v[j] * v[j]; }
#pragma unroll
            for (int off = 8; off > 0; off >>= 1) {
                s  += __shfl_xor_sync(0xffffffffu, s, off);
                sq += __shfl_xor_sync(0xffffffffu, sq, off);
            }
            float mu = s * (1.f / 128.f);
            float var = sq * (1.f / 128.f) - mu * mu;
            float rs = rsqrtf(var + 1e-5f);
            if (n < NN) {
                float o[8];
#pragma unroll
                for (int j = 0; j < 8; j++)
                    o[j] = (v[j] - mu) * rs * gg[j] + qq[j];
                *(float4*)&g_h[n * HID + c0]     = make_float4(o[0], o[1], o[2], o[3]);
                *(float4*)&g_h[n * HID + c0 + 4] = make_float4(o[4], o[5], o[6], o[7]);
            }
        }
    }
}

// ---------------- final readout (fp32 scalar; small) ----------------
__global__ void k_final(const float* __restrict__ gc,
                        const float* __restrict__ qw1,
                        const float* __restrict__ qb1,
                        const float* __restrict__ qw2,
                        const float* __restrict__ qb2p,
                        float* __restrict__ out) {
    __shared__ float sA[32 * 33];
    __shared__ float sW[128 * 33];
    __shared__ float sctx[64];
    __shared__ float sout[32];
    int tid = threadIdx.x;
    int n0 = blockIdx.x * 32;
    if (tid < 64) sctx[tid] = gc[tid];
    if (tid < 32) sout[tid] = qb2p[0];
    __syncthreads();
    int tc = tid & 31, trg = tid >> 5;
    float acc[4][4] = {};
    for (int kb = 0; kb < 192; kb += 32) {
        for (int idx = tid; idx < 32 * 32; idx += NT) {
            int r = idx >> 5, kk = idx & 31;
            int n = n0 + r;
            int kg = kb + kk;
            float v = 0.f;
            if (n < NN) v = (kg < 128) ? g_h[n * HID + kg] : sctx[kg - 128];
            sA[r * 33 + kk] = v;
        }
        for (int idx = tid; idx < 128 * 32; idx += NT) {
            int o = idx >> 5, kk = idx & 31;
            sW[o * 33 + kk] = qw1[o * 192 + kb + kk];
        }
        __syncthreads();
#pragma unroll 8
        for (int k = 0; k < 32; k++) {
            float a[4], w[4];
#pragma unroll
            for (int i = 0; i < 4; i++) a[i] = sA[(trg * 4 + i) * 33 + k];
#pragma unroll
            for (int j = 0; j < 4; j++) w[j] = sW[(tc + 32 * j) * 33 + k];
#pragma unroll
            for (int i = 0; i < 4; i++)
#pragma unroll
                for (int j = 0; j < 4; j++) acc[i][j] += a[i] * w[j];
        }
        __syncthreads();
    }
    float p[4] = {0.f, 0.f, 0.f, 0.f};
#pragma unroll
    for (int j = 0; j < 4; j++) {
        int c = tc + 32 * j;
        float b = qb1[c], w2 = qw2[c];
#pragma unroll
        for (int i = 0; i < 4; i++) {
            float v = fmaxf(acc[i][j] + b, 0.f);
            p[i] += v * w2;
        }
    }
#pragma unroll
    for (int i = 0; i < 4; i++) atomicAdd(&sout[trg * 4 + i], p[i]);
    __syncthreads();
    if (tid < 32) {
        int n = n0 + tid;
        if (n < NN) out[n] = sout[tid];
    }
}

// ---------------- launch ----------------
extern "C" void kernel_launch(void* const* d_in, const int* in_sizes, int n_in,
                              void* d_out, int out_size) {
    const float* x    = (const float*)d_in[0];
    const void*  eidx = d_in[1];
    const float* ea   = (const float*)d_in[2];
    const float* gc   = (const float*)d_in[3];
    const float* npw  = (const float*)d_in[4];
    const float* npb  = (const float*)d_in[5];
    const float* mw1  = (const float*)d_in[6];
    const float* mb1  = (const float*)d_in[7];
    const float* mw2  = (const float*)d_in[8];
    const float* mb2  = (const float*)d_in[9];
    const float* aw1  = (const float*)d_in[10];
    const float* ab1  = (const float*)d_in[11];
    const float* aw2  = (const float*)d_in[12];
    const float* ab2  = (const float*)d_in[13];
    const float* uw1  = (const float*)d_in[14];
    const float* ub1  = (const float*)d_in[15];
    const float* uw2  = (const float*)d_in[16];
    const float* ub2  = (const float*)d_in[17];
    const float* lng  = (const float*)d_in[18];
    const float* lnb  = (const float*)d_in[19];
    const float* qw1  = (const float*)d_in[20];
    const float* qb1  = (const float*)d_in[21];
    const float* qw2  = (const float*)d_in[22];
    const float* qb2  = (const float*)d_in[23];
    float* out = (float*)d_out;

    const int smem_msg = (16 * 132 + 16 * 128 + 128 * 132) * 4 + 128 * 3 * 4;
    const int smem_upd = (16 * 132 + 16 * 128 + 128 * 132) * 4;
    cudaFuncSetAttribute(k_msg, cudaFuncAttributeMaxDynamicSharedMemorySize, smem_msg);
    cudaFuncSetAttribute(k_update, cudaFuncAttributeMaxDynamicSharedMemorySize, smem_upd);

    k_detect<<<1, NT>>>((const unsigned*)eidx);
    k_convert<<<(NE + NT - 1) / NT, NT>>>(eidx);
    k_nodeproj<<<(NN + 31) / 32, NT>>>(x, npw, npb);

    for (int l = 0; l < 3; l++) {
        k_reset<<<1024, NT>>>();
        k_attn<<<(NE + 255) / 256, NT>>>(ea, aw1 + l * 64 * 272, ab1 + l * 64,
                                         aw2 + l * 64, ab2 + l);
        k_exp<<<(NE + NT - 1) / NT, NT>>>();
        k_msg<<<(NE + 127) / 128, NT, smem_msg>>>(ea, mw1 + l * 128 * 144, mb1 + l * 128,
                                                  mw2 + l * 128 * 128, mb2 + l * 128);
        k_update<<<(NN + 127) / 128, NT, smem_upd>>>(uw1 + l * 128 * 256, ub1 + l * 128,
                                                     uw2 + l * 128 * 128, ub2 + l * 128,
                                                     lng + l * 128, lnb + l * 128);
    }
    k_final<<<(NN + 31) / 32, NT>>>(gc, qw1, qb1, qw2, qb2, out);
}